// round 6
// baseline (speedup 1.0000x reference)
#include <cuda_runtime.h>

// FocalBCELoss: mean over [N,C] of -( t*log(p)*(1-p)^2*alpha[c] + (1-t)*log(1-p)*p^2 )
// N=262144, C=64, gamma=2.0 (powers become multiplies).
// Streaming HBM-bound reduction: 128 MiB read -> scalar.

#define FB_N       262144
#define FB_C       64
#define FB_TOTAL   (FB_N * FB_C)          // 16,777,216
#define FB_N4      (FB_TOTAL / 4)         // 4,194,304 float4s (exact)

#define RED_BLOCKS  1184                  // 148 SMs * 8
#define RED_THREADS 256

__device__ float g_partials[RED_BLOCKS];

__device__ __forceinline__ float focal_elem(float p, float t, float a) {
    float omp = 1.0f - p;
    float lp  = __logf(p);     // MUFU.LG2 path
    float lq  = __logf(omp);
    float pos = lp * (omp * omp) * a;   // targets==1 branch
    float neg = lq * (p * p);           // targets==0 branch
    // t is exactly 0.0 or 1.0 -> branchless select
    return fmaf(t, pos - neg, neg);
}

__global__ __launch_bounds__(RED_THREADS)
void focal_partial_kernel(const float4* __restrict__ in4,
                          const float4* __restrict__ tg4,
                          const float*  __restrict__ alpha) {
    const int tid    = blockIdx.x * RED_THREADS + threadIdx.x;
    const int stride = RED_BLOCKS * RED_THREADS;   // float4 stride; *4 floats divisible by 64
    // Column base is constant per thread (stride*4 % 64 == 0, row = 16 float4s)
    const int cb = (tid * 4) & (FB_C - 1);
    const float a0 = __ldg(alpha + cb + 0);
    const float a1 = __ldg(alpha + cb + 1);
    const float a2 = __ldg(alpha + cb + 2);
    const float a3 = __ldg(alpha + cb + 3);

    float acc = 0.0f;
    for (int i = tid; i < FB_N4; i += stride) {
        float4 p = __ldg(in4 + i);
        float4 t = __ldg(tg4 + i);
        acc += focal_elem(p.x, t.x, a0);
        acc += focal_elem(p.y, t.y, a1);
        acc += focal_elem(p.z, t.z, a2);
        acc += focal_elem(p.w, t.w, a3);
    }

    // warp reduce
    #pragma unroll
    for (int off = 16; off > 0; off >>= 1)
        acc += __shfl_down_sync(0xFFFFFFFFu, acc, off);

    __shared__ float smem[RED_THREADS / 32];
    const int lane = threadIdx.x & 31;
    const int wid  = threadIdx.x >> 5;
    if (lane == 0) smem[wid] = acc;
    __syncthreads();

    if (wid == 0) {
        float v = (lane < RED_THREADS / 32) ? smem[lane] : 0.0f;
        #pragma unroll
        for (int off = 4; off > 0; off >>= 1)
            v += __shfl_down_sync(0xFFFFFFFFu, v, off);
        if (lane == 0) g_partials[blockIdx.x] = v;
    }
}

__global__ __launch_bounds__(RED_THREADS)
void focal_final_kernel(float* __restrict__ out) {
    float acc = 0.0f;
    for (int i = threadIdx.x; i < RED_BLOCKS; i += RED_THREADS)
        acc += g_partials[i];

    #pragma unroll
    for (int off = 16; off > 0; off >>= 1)
        acc += __shfl_down_sync(0xFFFFFFFFu, acc, off);

    __shared__ float smem[RED_THREADS / 32];
    const int lane = threadIdx.x & 31;
    const int wid  = threadIdx.x >> 5;
    if (lane == 0) smem[wid] = acc;
    __syncthreads();

    if (wid == 0) {
        float v = (lane < RED_THREADS / 32) ? smem[lane] : 0.0f;
        #pragma unroll
        for (int off = 4; off > 0; off >>= 1)
            v += __shfl_down_sync(0xFFFFFFFFu, v, off);
        if (lane == 0)
            out[0] = -v * (1.0f / (float)FB_TOTAL);
    }
}

extern "C" void kernel_launch(void* const* d_in, const int* in_sizes, int n_in,
                              void* d_out, int out_size) {
    const float4* in4   = (const float4*)d_in[0];   // inputs  [N,C] f32
    const float4* tg4   = (const float4*)d_in[1];   // targets [N,C] f32
    const float*  alpha = (const float*)d_in[2];    // alpha   [C]   f32
    float* out = (float*)d_out;

    focal_partial_kernel<<<RED_BLOCKS, RED_THREADS>>>(in4, tg4, alpha);
    focal_final_kernel<<<1, RED_THREADS>>>(out);
}